// round 14
// baseline (speedup 1.0000x reference)
#include <cuda_runtime.h>
#include <math.h>

#define NN 65536
#define EE 262144
#define NPGS 8192
#define GRID 296
#define TPB 256
#define NT (GRID * TPB)
#define SLICE4 222            // int4 loads per block slice (222*4 = 888 edges)
#define E0CAP 888
#define E1CAP 384
#define NSUB 8
#define SUBSZ (GRID / NSUB)   // 37
#define NEG_INF __int_as_float(0xff800000)

// ---------------- scratch (device globals; canonical state between replays = all zeros) ----
__device__ __align__(16) int            g_m1[NN], g_m0[NN];
__device__ __align__(16) unsigned char  g_m1b[NN], g_m0b[NN];
__device__ __align__(16) int   g_e1[EE], g_e2[EE];    // g_e1 = SPILL-only
__device__ __align__(16) int   g_s0[NN], g_s1[NN];
__device__ __align__(16) int   g_cnt[8];    // 0:nE2 1:nE1spill 3:nS0 4:nS1 (zeroed by cleanup)
__device__ __align__(16) int   g_cntS[8];   // shadow for final phase
__device__ int   g_spos1[8];                 // S1 list position of each seed
__device__ __align__(16) float g_h0[NN * 128];
__device__ __align__(16) float g_h1[NN * 256];   // layer-1 message numerator
__device__ __align__(16) float g_q[NN * 256];
__device__ __align__(16) float g_k[NN * 256];
__device__ __align__(16) float g_v[NN * 256];
__device__ __align__(16) float g_t1[NN * 256];   // skip GEMV, indexed by S1 list position
__device__ __align__(16) float g_t2[8 * 256];
__device__ __align__(16) float g_amax[NN * 4];
__device__ __align__(16) float g_asum[NN * 4];
__device__ __align__(16) float g_alpha[EE];      // spill-path alphas only

// two-level tree barrier (8 padded subgroup counters -> master -> generation flag)
__device__ __align__(128) unsigned g_bar_sub[NSUB * 32];   // 128B stride per counter
__device__ unsigned          g_bar_cnt;
__device__ volatile unsigned g_bar_gen;

__device__ __forceinline__ void gsync(int bid) {
    __syncthreads();
    if (threadIdx.x == 0) {
        __threadfence();
        unsigned gen = g_bar_gen;
        if (atomicAdd(&g_bar_sub[(bid & (NSUB - 1)) * 32], 1u) == SUBSZ - 1) {
            g_bar_sub[(bid & (NSUB - 1)) * 32] = 0;   // reset before master; safe (see post-mortem)
            if (atomicAdd(&g_bar_cnt, 1u) == NSUB - 1) {
                g_bar_cnt = 0;
                __threadfence();
                g_bar_gen = gen + 1;
            }
        }
        int spins = 0;
        while (g_bar_gen == gen) {
            if (++spins > 64) { __nanosleep(16); spins = 0; }
        }
        __threadfence();
    }
    __syncthreads();
}

__device__ __forceinline__ void atomicMaxF(float* a, float v) {
    if (v >= 0.0f) atomicMax((int*)a, __float_as_int(v));
    else           atomicMin((unsigned int*)a, __float_as_uint(v));
}

__device__ __forceinline__ void zero_row_h1(int n) {
    float4 z = make_float4(0.f, 0.f, 0.f, 0.f);
    float4* p = (float4*)&g_h1[n * 256];
    #pragma unroll 8
    for (int q = 0; q < 64; q++) p[q] = z;
    ((float4*)&g_amax[n * 4])[0] = make_float4(NEG_INF, NEG_INF, NEG_INF, NEG_INF);
    ((float4*)&g_asum[n * 4])[0] = z;
}
__device__ __forceinline__ void zero_row_h0(int n) {
    float4 z = make_float4(0.f, 0.f, 0.f, 0.f);
    float4* p = (float4*)&g_h0[n * 128];
    #pragma unroll 8
    for (int q = 0; q < 32; q++) p[q] = z;
}

__device__ __forceinline__ void insert_s1(int s, const int* sa) {
    if (atomicExch(&g_m1[s], 1) == 0) {
        g_m1b[s] = 1;
        int p = atomicAdd(&g_cnt[4], 1);
        g_s1[p] = s;
        if ((s & 8191) == sa[s >> 13]) g_spos1[s >> 13] = p;
        zero_row_h1(s);
    }
}
__device__ __forceinline__ void insert_s0(int s) {
    if (atomicExch(&g_m0[s], 1) == 0) {
        g_m0b[s] = 1;
        g_s0[atomicAdd(&g_cnt[3], 1)] = s;
        zero_row_h0(s);
    }
}

// h1 final value on the fly: relu(num/asum + t1[list_pos])
__device__ __forceinline__ float h1val(int n, int i, int j) {
    return fmaxf(g_h1[n * 256 + j] / (g_asum[n * 4 + (j >> 6)] + 1e-16f)
                 + g_t1[i * 256 + j], 0.f);
}

// ==================== single persistent megakernel ====================
__global__ void __launch_bounds__(TPB, 2)
k_mega(const float* __restrict__ x, const int* __restrict__ esrc,
       const int* __restrict__ edst, const float* __restrict__ eattr,
       const int* __restrict__ aid, const float* __restrict__ emb,
       const float* __restrict__ w1, const float* __restrict__ b1,
       const float* __restrict__ wh, const float* __restrict__ bh,
       const float* __restrict__ q1w, const float* __restrict__ q1b,
       const float* __restrict__ k1w, const float* __restrict__ k1b,
       const float* __restrict__ v1w, const float* __restrict__ v1b,
       const float* __restrict__ e1w,
       const float* __restrict__ s1w, const float* __restrict__ s1b,
       const float* __restrict__ q2w, const float* __restrict__ q2b,
       const float* __restrict__ k2w, const float* __restrict__ k2b,
       const float* __restrict__ v2w, const float* __restrict__ v2b,
       const float* __restrict__ e2w,
       const float* __restrict__ s2w, const float* __restrict__ s2b,
       float* __restrict__ out) {
    __shared__ int   sa[8];
    __shared__ int   e0loc[E0CAP];                  // block-local E0 edge list
    __shared__ int   e1loc[E1CAP];                  // block-local E1 edge list
    __shared__ float al1[E1CAP * 4];                // local alphas per head
    __shared__ int   nloc0_sh, nloc1_sh;
    __shared__ __align__(16) float sint[8][52];
    __shared__ __align__(16) float szt[8][128];
    __shared__ int   ss8[8], ds8[8], sent8[8];
    __shared__ float sea8[8];
    __shared__ __align__(16) float hrowA[2][128];
    __shared__ __align__(16) float hq1[4][128];
    __shared__ __align__(16) float hrowB[2][256];
    __shared__ __align__(16) float hq2[4][256];
    __shared__ int   nsA[2], niA[2], nsB[4], spB[4];
    __shared__ int   sd_all[256], ss_all[256];
    __shared__ float sea_all[256];
    __shared__ int   ssrc_s[64];
    __shared__ float seaa[64];
    __shared__ float sal[4][64];
    __shared__ int   ne_sh;

    int tid = threadIdx.x, bid = blockIdx.x;
    int gt  = bid * TPB + tid;
    int wid = tid >> 5, lane = tid & 31;

    if (tid < 8) sa[tid] = aid[tid];
    __syncthreads();

    // slice bounds (int4 units) for block-local scans
    int sl_beg = bid * SLICE4;
    int sl_end = min(EE / 4, sl_beg + SLICE4);

    // ---------- phase 1: seeds + scan2 (dst in S2 arithmetically; grow S1, S0) ----------
    if (bid == 0 && tid < 8) {
        int n = tid * NPGS + sa[tid];
        insert_s1(n, sa);
        insert_s0(n);
    }
    for (int t = gt; t < EE / 4; t += NT) {
        int4 d4 = ((const int4*)edst)[t];
        int dd[4] = {d4.x, d4.y, d4.z, d4.w};
        #pragma unroll
        for (int j = 0; j < 4; j++) {
            int d = dd[j];
            if ((d & 8191) == sa[d >> 13]) {
                int e = t * 4 + j;
                g_e2[atomicAdd(&g_cnt[0], 1)] = e;
                int s = esrc[e];
                insert_s1(s, sa);
                insert_s0(s);
            }
        }
    }
    gsync(bid);

    // ---------- phase 2: scan1 over block slice -> local E1 list; grow S0 ----------
    if (tid == 0) nloc1_sh = 0;
    __syncthreads();
    for (int t = sl_beg + tid; t < sl_end; t += TPB) {
        int4 d4 = ((const int4*)edst)[t];
        int dd[4] = {d4.x, d4.y, d4.z, d4.w};
        #pragma unroll
        for (int j = 0; j < 4; j++) {
            if (g_m1b[dd[j]]) {
                int e = t * 4 + j;
                int p = atomicAdd(&nloc1_sh, 1);
                if (p < E1CAP) e1loc[p] = e;
                else           g_e1[atomicAdd(&g_cnt[1], 1)] = e;   // spill (≈never)
                insert_s0(esrc[e]);
            }
        }
    }
    gsync(bid);
    int nloc1 = min(nloc1_sh, E1CAP);

    // ---------- phase 3: scan0 over block slice -> local E0 list, then MLP -> h0 ----------
    {
        if (tid == 0) nloc0_sh = 0;
        __syncthreads();
        for (int t = sl_beg + tid; t < sl_end; t += TPB) {
            int4 d4 = ((const int4*)edst)[t];
            int dd[4] = {d4.x, d4.y, d4.z, d4.w};
            #pragma unroll
            for (int j = 0; j < 4; j++) {
                if (g_m0b[dd[j]]) e0loc[atomicAdd(&nloc0_sh, 1)] = t * 4 + j;
            }
        }
        __syncthreads();
        int nloc0 = nloc0_sh;   // capacity E0CAP == slice size, cannot overflow
        int slot = tid >> 5;            // 8 edge slots x 32 threads
        int c4   = (tid & 31) * 4;      // 128 cols / 4
        for (int base = 0; base < nloc0; base += 8) {
            int ne = min(8, nloc0 - base);
            if (tid < ne) {
                int e = e0loc[base + tid];
                int s = esrc[e];
                ss8[tid] = s; ds8[tid] = edst[e]; sea8[tid] = eattr[e];
                sent8[tid] = (int)x[s * 36 + 35];
            }
            __syncthreads();
            for (int idx = tid; idx < 8 * 52; idx += TPB) {
                int sl = idx / 52, j = idx % 52;
                float v = 0.f;
                if (sl < ne) {
                    if (j < 35)      v = x[ss8[sl] * 36 + j];
                    else if (j < 51) v = emb[sent8[sl] * 16 + (j - 35)];
                    else             v = sea8[sl];
                }
                sint[sl][j] = v;
            }
            __syncthreads();
            float4 acc = *(const float4*)&b1[c4];
            #pragma unroll 4
            for (int j = 0; j < 52; j++) {
                float4 w = *(const float4*)&w1[j * 128 + c4];
                float h = sint[slot][j];
                acc.x += h * w.x; acc.y += h * w.y; acc.z += h * w.z; acc.w += h * w.w;
            }
            acc.x = fmaxf(acc.x, 0.f); acc.y = fmaxf(acc.y, 0.f);
            acc.z = fmaxf(acc.z, 0.f); acc.w = fmaxf(acc.w, 0.f);
            *(float4*)&szt[slot][c4] = acc;
            __syncthreads();
            float4 a2 = *(const float4*)&bh[c4];
            #pragma unroll 16
            for (int j = 0; j < 128; j++) {
                float4 w = *(const float4*)&wh[j * 128 + c4];
                float h = szt[slot][j];
                a2.x += h * w.x; a2.y += h * w.y; a2.z += h * w.z; a2.w += h * w.w;
            }
            if (slot < ne) {
                float* hp = &g_h0[ds8[slot] * 128 + c4];
                atomicAdd(hp + 0, fmaxf(a2.x, 0.f));
                atomicAdd(hp + 1, fmaxf(a2.y, 0.f));
                atomicAdd(hp + 2, fmaxf(a2.z, 0.f));
                atomicAdd(hp + 3, fmaxf(a2.w, 0.f));
            }
            __syncthreads();
        }
    }
    gsync(bid);

    // ---------- phase 4: k,v over S0 (blocks 0-255) || q over S1 (blocks 256-295) ----------
    {
        int cntS0 = *(volatile int*)&g_cnt[3];
        int cntS1 = *(volatile int*)&g_cnt[4];
        if (bid < 256) {
            int slot = tid >> 7;            // 2 nodes/pass
            int m    = (tid >> 6) & 1;      // 0=k, 1=v
            int c4   = (tid & 63) * 4;
            const float* W  = m ? v1w : k1w;
            const float* Bb = m ? v1b : k1b;
            for (int base = bid * 2; base < cntS0; base += 256 * 2) {
                if (tid < 2) nsA[tid] = g_s0[min(base + tid, cntS0 - 1)];
                __syncthreads();
                for (int idx = tid; idx < 256; idx += TPB)
                    hrowA[idx >> 7][idx & 127] = g_h0[nsA[idx >> 7] * 128 + (idx & 127)];
                __syncthreads();
                float4 acc = *(const float4*)&Bb[c4];
                #pragma unroll 16
                for (int j = 0; j < 128; j++) {
                    float4 w = *(const float4*)&W[j * 256 + c4];
                    float h = hrowA[slot][j];
                    acc.x += h * w.x; acc.y += h * w.y; acc.z += h * w.z; acc.w += h * w.w;
                }
                if (base + slot < cntS0)
                    *(float4*)((m ? g_v : g_k) + nsA[slot] * 256 + c4) = acc;
                __syncthreads();
            }
        } else {
            int bq = bid - 256;             // 0..39
            int slot = tid >> 6;            // 4 nodes/pass
            int c4 = (tid & 63) * 4;
            for (int base = bq * 4; base < cntS1; base += 40 * 4) {
                if (tid < 4) nsB[tid] = g_s1[min(base + tid, cntS1 - 1)];
                __syncthreads();
                for (int idx = tid; idx < 512; idx += TPB)
                    hq1[idx >> 7][idx & 127] = g_h0[nsB[idx >> 7] * 128 + (idx & 127)];
                __syncthreads();
                float4 acc = *(const float4*)&q1b[c4];
                #pragma unroll 16
                for (int j = 0; j < 128; j++) {
                    float4 w = *(const float4*)&q1w[j * 256 + c4];
                    float h = hq1[slot][j];
                    acc.x += h * w.x; acc.y += h * w.y; acc.z += h * w.z; acc.w += h * w.w;
                }
                if (base + slot < cntS1)
                    *(float4*)&g_q[nsB[slot] * 256 + c4] = acc;
                __syncthreads();
            }
        }
    }
    gsync(bid);

    // ---------- phase 5: local alpha+amax || spill alpha || t1 (ALL blocks) ----------
    {
        for (int p = wid; p < nloc1 * 4; p += 8) {
            int k = p >> 2, h = p & 3;
            int e = e1loc[k];
            int s = esrc[e], d = edst[e];
            float ea = eattr[e];
            float d0 = 0.f;
            #pragma unroll
            for (int c0 = 0; c0 < 2; c0++) {
                int c = lane + c0 * 32;
                d0 += g_q[d * 256 + h * 64 + c] * (g_k[s * 256 + h * 64 + c] + ea * e1w[h * 64 + c]);
            }
            #pragma unroll
            for (int o = 16; o; o >>= 1) d0 += __shfl_xor_sync(0xffffffffu, d0, o);
            if (lane == 0) {
                float a = d0 * 0.125f;
                al1[k * 4 + h] = a;
                atomicMaxF(&g_amax[d * 4 + h], a);
            }
        }
        int nsp = *(volatile int*)&g_cnt[1];
        for (int t = gt; t < nsp * 4; t += NT) {
            int i = t >> 2, h = t & 3;
            int e = g_e1[i];
            int s = esrc[e], d = edst[e];
            float ea = eattr[e];
            const float4* qp = (const float4*)(g_q + d * 256 + h * 64);
            const float4* kp = (const float4*)(g_k + s * 256 + h * 64);
            const float4* ep = (const float4*)(e1w + h * 64);
            float dot = 0.f;
            #pragma unroll
            for (int c = 0; c < 16; c++) {
                float4 q = qp[c], k = kp[c], w = ep[c];
                dot += q.x * (k.x + ea * w.x) + q.y * (k.y + ea * w.y)
                     + q.z * (k.z + ea * w.z) + q.w * (k.w + ea * w.w);
            }
            float a = dot * 0.125f;
            g_alpha[t] = a;
            atomicMaxF(&g_amax[d * 4 + h], a);
        }
        int cntS1 = *(volatile int*)&g_cnt[4];
        int slot = tid >> 6;
        int c4 = (tid & 63) * 4;
        for (int base = bid * 4; base < cntS1; base += GRID * 4) {
            if (tid < 4) nsB[tid] = g_s1[min(base + tid, cntS1 - 1)];
            __syncthreads();
            for (int idx = tid; idx < 512; idx += TPB)
                hq1[idx >> 7][idx & 127] = g_h0[nsB[idx >> 7] * 128 + (idx & 127)];
            __syncthreads();
            float4 acc = *(const float4*)&s1b[c4];
            #pragma unroll 16
            for (int j = 0; j < 128; j++) {
                float4 w = *(const float4*)&s1w[j * 256 + c4];
                float h = hq1[slot][j];
                acc.x += h * w.x; acc.y += h * w.y; acc.z += h * w.z; acc.w += h * w.w;
            }
            if (base + slot < cntS1)
                *(float4*)&g_t1[(base + slot) * 256 + c4] = acc;
            __syncthreads();
        }
    }
    gsync(bid);

    // ---------- phase 6: exp + sum + unnormalized message -> g_h1 (local + spill) ----------
    {
        int h = tid >> 6;
        for (int i = 0; i < nloc1; i++) {
            int e = e1loc[i];
            int s = esrc[e], d = edst[e];
            float ea = eattr[e];
            float ex = expf(al1[i * 4 + h] - g_amax[d * 4 + h]);
            if ((tid & 63) == 0) atomicAdd(&g_asum[d * 4 + h], ex);
            atomicAdd(&g_h1[d * 256 + tid], (g_v[s * 256 + tid] + ea * e1w[tid]) * ex);
        }
        int nsp = *(volatile int*)&g_cnt[1];
        for (int i = bid; i < nsp; i += GRID) {
            int e = g_e1[i];
            int s = esrc[e], d = edst[e];
            float ea = eattr[e];
            float ex = expf(g_alpha[i * 4 + h] - g_amax[d * 4 + h]);
            if ((tid & 63) == 0) atomicAdd(&g_asum[d * 4 + h], ex);
            atomicAdd(&g_h1[d * 256 + tid], (g_v[s * 256 + tid] + ea * e1w[tid]) * ex);
        }
    }
    gsync(bid);

    // ---------- phase 7: kv2 over S1 (blocks 0-199) || q2 seeds (200-201)
    //                      || t2 seeds (202-203) || shadow counters (204) ----------
    {
        int cntS1 = *(volatile int*)&g_cnt[4];
        if (bid < 200) {
            int slot = tid >> 7;
            int m    = (tid >> 6) & 1;
            int c4   = (tid & 63) * 4;
            const float* W  = m ? v2w : k2w;
            const float* Bb = m ? v2b : k2b;
            for (int base = bid * 2; base < cntS1; base += 200 * 2) {
                if (tid < 2) {
                    int ii = min(base + tid, cntS1 - 1);
                    niA[tid] = ii; nsA[tid] = g_s1[ii];
                }
                __syncthreads();
                for (int idx = tid; idx < 512; idx += TPB) {
                    int sl = idx >> 8, j = idx & 255;
                    hrowB[sl][j] = h1val(nsA[sl], niA[sl], j);
                }
                __syncthreads();
                float4 acc = *(const float4*)&Bb[c4];
                #pragma unroll 16
                for (int j = 0; j < 256; j++) {
                    float4 w = *(const float4*)&W[j * 256 + c4];
                    float h = hrowB[slot][j];
                    acc.x += h * w.x; acc.y += h * w.y; acc.z += h * w.z; acc.w += h * w.w;
                }
                if (base + slot < cntS1)
                    *(float4*)((m ? g_v : g_k) + nsA[slot] * 256 + c4) = acc;
                __syncthreads();
            }
        } else if (bid < 204) {
            bool is_t = bid >= 202;
            int bq = (bid - (is_t ? 202 : 200));   // 0..1 -> seeds 0-3 / 4-7
            int slot = tid >> 6;
            int c4 = (tid & 63) * 4;
            int seed = bq * 4 + slot;
            if (tid < 4) {
                int sd = bq * 4 + tid;
                spB[tid] = g_spos1[sd];
                nsB[tid] = sd * NPGS + sa[sd];
            }
            __syncthreads();
            for (int idx = tid; idx < 1024; idx += TPB) {
                int sl = idx >> 8, j = idx & 255;
                hq2[sl][j] = h1val(nsB[sl], spB[sl], j);
            }
            __syncthreads();
            const float* W  = is_t ? s2w : q2w;
            const float* Bb = is_t ? s2b : q2b;
            float4 acc = *(const float4*)&Bb[c4];
            #pragma unroll 16
            for (int j = 0; j < 256; j++) {
                float4 w = *(const float4*)&W[j * 256 + c4];
                float h = hq2[slot][j];
                acc.x += h * w.x; acc.y += h * w.y; acc.z += h * w.z; acc.w += h * w.w;
            }
            if (is_t) *(float4*)&g_t2[seed * 256 + c4] = acc;
            else      *(float4*)&g_q[nsB[slot] * 256 + c4] = acc;
        } else if (bid == 204 && tid < 8) {
            g_cntS[tid] = g_cnt[tid];     // shadow for final phase
        }
    }
    gsync(bid);

    // ---------- phase 8: attention+output (blocks 0-7) || cleanup (blocks 8+) ----------
    if (bid < 8) {
        int b = bid;
        int n = b * NPGS + sa[b];
        int cnt = g_cntS[0]; if (cnt > 256) cnt = 256;
        if (tid < cnt) {
            int e = g_e2[tid];
            sd_all[tid] = edst[e]; ss_all[tid] = esrc[e]; sea_all[tid] = eattr[e];
        }
        __syncthreads();
        if (tid == 0) {
            int p = 0;
            for (int i = 0; i < cnt; i++)
                if ((sd_all[i] >> 13) == b && p < 64) { ssrc_s[p] = ss_all[i]; seaa[p] = sea_all[i]; p++; }
            ne_sh = p;
        }
        __syncthreads();
        int ne = ne_sh;
        for (int p = wid; p < ne * 4; p += 8) {
            int k = p >> 2, h = p & 3;
            int s = ssrc_s[k]; float ea = seaa[k];
            float d0 = 0.f;
            #pragma unroll
            for (int c0 = 0; c0 < 2; c0++) {
                int c = lane + c0 * 32;
                d0 += g_q[n * 256 + h * 64 + c] * (g_k[s * 256 + h * 64 + c] + ea * e2w[h * 64 + c]);
            }
            #pragma unroll
            for (int o = 16; o; o >>= 1) d0 += __shfl_xor_sync(0xffffffffu, d0, o);
            if (lane == 0) sal[h][k] = d0 * 0.125f;
        }
        __syncthreads();
        if (tid < 4) {
            float m = NEG_INF;
            for (int k = 0; k < ne; k++) m = fmaxf(m, sal[tid][k]);
            float s = 0.f;
            for (int k = 0; k < ne; k++) { float ex = expf(sal[tid][k] - m); sal[tid][k] = ex; s += ex; }
            float inv = 1.f / (s + 1e-16f);
            for (int k = 0; k < ne; k++) sal[tid][k] *= inv;
        }
        __syncthreads();
        int h = tid >> 6;
        float acc = 0.f;
        for (int k = 0; k < ne; k++)
            acc += (g_v[ssrc_s[k] * 256 + tid] + seaa[k] * e2w[tid]) * sal[h][k];
        out[b * 256 + tid] = fmaxf(acc + g_t2[b * 256 + tid], 0.f);
    } else {
        // cleanup: restore canonical all-zero flag/counter state for the next replay
        int c0 = g_cntS[3], c1 = g_cntS[4];
        for (int i = (bid - 8) * TPB + tid; i < c0; i += (GRID - 8) * TPB) {
            int nn2 = g_s0[i];
            g_m0[nn2] = 0; g_m0b[nn2] = 0;
        }
        for (int i = (bid - 8) * TPB + tid; i < c1; i += (GRID - 8) * TPB) {
            int nn2 = g_s1[i];
            g_m1[nn2] = 0; g_m1b[nn2] = 0;
        }
        if (bid == 8 && tid < 8) g_cnt[tid] = 0;
    }
}

// ---------------- launch ----------------
extern "C" void kernel_launch(void* const* d_in, const int* in_sizes, int n_in,
                              void* d_out, int out_size) {
    const float* x     = (const float*)d_in[0];
    const int*   esrc  = (const int*)d_in[1];
    const int*   edst  = (const int*)d_in[2];
    const float* eattr = (const float*)d_in[3];
    const int*   aid   = (const int*)d_in[4];
    const float* emb   = (const float*)d_in[5];
    const float* w1    = (const float*)d_in[6];
    const float* b1    = (const float*)d_in[7];
    const float* wh    = (const float*)d_in[8];
    const float* bh    = (const float*)d_in[9];
    const float* q1w = (const float*)d_in[10], *q1b = (const float*)d_in[11];
    const float* k1w = (const float*)d_in[12], *k1b = (const float*)d_in[13];
    const float* v1w = (const float*)d_in[14], *v1b = (const float*)d_in[15];
    const float* e1w = (const float*)d_in[16];
    const float* s1w = (const float*)d_in[17], *s1b = (const float*)d_in[18];
    const float* q2w = (const float*)d_in[19], *q2b = (const float*)d_in[20];
    const float* k2w = (const float*)d_in[21], *k2b = (const float*)d_in[22];
    const float* v2w = (const float*)d_in[23], *v2b = (const float*)d_in[24];
    const float* e2w = (const float*)d_in[25];
    const float* s2w = (const float*)d_in[26], *s2b = (const float*)d_in[27];
    float* out = (float*)d_out;

    k_mega<<<GRID, TPB>>>(x, esrc, edst, eattr, aid, emb, w1, b1, wh, bh,
                          q1w, q1b, k1w, k1b, v1w, v1b, e1w, s1w, s1b,
                          q2w, q2b, k2w, k2b, v2w, v2b, e2w, s2w, s2b, out);
}

// round 15
// speedup vs baseline: 1.0616x; 1.0616x over previous
#include <cuda_runtime.h>
#include <math.h>

#define NN 65536
#define EE 262144
#define NPGS 8192
#define GRID 296
#define TPB 256
#define NT (GRID * TPB)
#define SLICE4 222            // int4 loads per block slice (222*4 = 888 edges)
#define E0CAP 888
#define E1CAP 384
#define NEG_INF __int_as_float(0xff800000)

// ---------------- scratch (device globals; canonical state between replays = all zeros) ----
__device__ __align__(16) int            g_m1[NN], g_m0[NN];
__device__ __align__(16) unsigned char  g_m1b[NN], g_m0b[NN];
__device__ __align__(16) int   g_e1[EE], g_e2[EE];    // g_e1 = SPILL-only
__device__ __align__(16) int   g_s0[NN], g_s1[NN];
__device__ __align__(16) int   g_cnt[8];    // 0:nE2 1:nE1spill 3:nS0 4:nS1 (zeroed by cleanup)
__device__ __align__(16) int   g_cntS[8];   // shadow for final phase
__device__ int   g_spos1[8];                 // S1 list position of each seed
__device__ __align__(16) float g_h0[NN * 128];
__device__ __align__(16) float g_h1[NN * 256];   // layer-1 message numerator
__device__ __align__(16) float g_q[NN * 256];
__device__ __align__(16) float g_k[NN * 256];
__device__ __align__(16) float g_v[NN * 256];
__device__ __align__(16) float g_t1[NN * 256];   // skip GEMV, indexed by S1 list position
__device__ __align__(16) float g_t2[8 * 256];
__device__ __align__(16) float g_amax[NN * 4];
__device__ __align__(16) float g_asum[NN * 4];
__device__ __align__(16) float g_alpha[EE];      // spill-path alphas only

// software grid barrier (generation-based; generation persists across replays)
__device__ unsigned          g_bar_cnt;
__device__ volatile unsigned g_bar_gen;

__device__ __forceinline__ void gsync() {
    __syncthreads();
    if (threadIdx.x == 0) {
        __threadfence();
        unsigned gen = g_bar_gen;
        if (atomicAdd(&g_bar_cnt, 1u) == GRID - 1) {
            g_bar_cnt = 0;
            __threadfence();
            g_bar_gen = gen + 1;
        } else {
            int spins = 0;
            while (g_bar_gen == gen) {
                if (++spins > 64) { __nanosleep(16); spins = 0; }
            }
            __threadfence();
        }
    }
    __syncthreads();
}

__device__ __forceinline__ void atomicMaxF(float* a, float v) {
    if (v >= 0.0f) atomicMax((int*)a, __float_as_int(v));
    else           atomicMin((unsigned int*)a, __float_as_uint(v));
}

__device__ __forceinline__ void zero_row_h1(int n) {
    float4 z = make_float4(0.f, 0.f, 0.f, 0.f);
    float4* p = (float4*)&g_h1[n * 256];
    #pragma unroll 8
    for (int q = 0; q < 64; q++) p[q] = z;
    ((float4*)&g_amax[n * 4])[0] = make_float4(NEG_INF, NEG_INF, NEG_INF, NEG_INF);
    ((float4*)&g_asum[n * 4])[0] = z;
}
__device__ __forceinline__ void zero_row_h0(int n) {
    float4 z = make_float4(0.f, 0.f, 0.f, 0.f);
    float4* p = (float4*)&g_h0[n * 128];
    #pragma unroll 8
    for (int q = 0; q < 32; q++) p[q] = z;
}

__device__ __forceinline__ void insert_s1(int s, const int* sa) {
    if (atomicExch(&g_m1[s], 1) == 0) {
        g_m1b[s] = 1;
        int p = atomicAdd(&g_cnt[4], 1);
        g_s1[p] = s;
        if ((s & 8191) == sa[s >> 13]) g_spos1[s >> 13] = p;
        zero_row_h1(s);
    }
}
__device__ __forceinline__ void insert_s0(int s) {
    if (atomicExch(&g_m0[s], 1) == 0) {
        g_m0b[s] = 1;
        g_s0[atomicAdd(&g_cnt[3], 1)] = s;
        zero_row_h0(s);
    }
}

// h1 final value on the fly: relu(num/asum + t1[list_pos])
__device__ __forceinline__ float h1val(int n, int i, int j) {
    return fmaxf(g_h1[n * 256 + j] / (g_asum[n * 4 + (j >> 6)] + 1e-16f)
                 + g_t1[i * 256 + j], 0.f);
}

// ==================== single persistent megakernel ====================
__global__ void __launch_bounds__(TPB, 2)
k_mega(const float* __restrict__ x, const int* __restrict__ esrc,
       const int* __restrict__ edst, const float* __restrict__ eattr,
       const int* __restrict__ aid, const float* __restrict__ emb,
       const float* __restrict__ w1, const float* __restrict__ b1,
       const float* __restrict__ wh, const float* __restrict__ bh,
       const float* __restrict__ q1w, const float* __restrict__ q1b,
       const float* __restrict__ k1w, const float* __restrict__ k1b,
       const float* __restrict__ v1w, const float* __restrict__ v1b,
       const float* __restrict__ e1w,
       const float* __restrict__ s1w, const float* __restrict__ s1b,
       const float* __restrict__ q2w, const float* __restrict__ q2b,
       const float* __restrict__ k2w, const float* __restrict__ k2b,
       const float* __restrict__ v2w, const float* __restrict__ v2b,
       const float* __restrict__ e2w,
       const float* __restrict__ s2w, const float* __restrict__ s2b,
       float* __restrict__ out) {
    __shared__ int   sa[8];
    __shared__ int   e0loc[E0CAP];                  // block-local E0 edge list
    __shared__ int   e1loc[E1CAP];                  // block-local E1 edge list
    __shared__ float al1[E1CAP * 4];                // local alphas per head
    __shared__ int   nloc0_sh, nloc1_sh;
    __shared__ __align__(16) float sint[8][52];
    __shared__ __align__(16) float szt[8][128];
    __shared__ int   ss8[8], ds8[8], sent8[8];
    __shared__ float sea8[8];
    __shared__ __align__(16) float hrowA[2][128];
    __shared__ __align__(16) float hq1[4][128];
    __shared__ __align__(16) float hrowB[2][256];
    __shared__ __align__(16) float hq2[4][256];
    __shared__ int   nsA[2], niA[2], nsB[4], spB[4];
    __shared__ int   sd_all[256], ss_all[256];
    __shared__ float sea_all[256];
    __shared__ int   ssrc_s[64];
    __shared__ float seaa[64];
    __shared__ float sal[4][64];
    __shared__ int   ne_sh;

    int tid = threadIdx.x, bid = blockIdx.x;
    int gt  = bid * TPB + tid;
    int wid = tid >> 5, lane = tid & 31;

    if (tid < 8) sa[tid] = aid[tid];
    __syncthreads();

    // slice bounds (int4 units) for block-local scans
    int sl_beg = bid * SLICE4;
    int sl_end = min(EE / 4, sl_beg + SLICE4);

    // ---------- phase 1: seeds + scan2 (dst in S2 arithmetically; grow S1, S0) ----------
    if (bid == 0 && tid < 8) {
        int n = tid * NPGS + sa[tid];
        insert_s1(n, sa);
        insert_s0(n);
    }
    for (int t = gt; t < EE / 4; t += NT) {
        int4 d4 = ((const int4*)edst)[t];
        int dd[4] = {d4.x, d4.y, d4.z, d4.w};
        #pragma unroll
        for (int j = 0; j < 4; j++) {
            int d = dd[j];
            if ((d & 8191) == sa[d >> 13]) {
                int e = t * 4 + j;
                g_e2[atomicAdd(&g_cnt[0], 1)] = e;
                int s = esrc[e];
                insert_s1(s, sa);
                insert_s0(s);
            }
        }
    }
    gsync();

    // ---------- phase 2: scan1 over block slice -> local E1 list; grow S0 ----------
    if (tid == 0) nloc1_sh = 0;
    __syncthreads();
    for (int t = sl_beg + tid; t < sl_end; t += TPB) {
        int4 d4 = ((const int4*)edst)[t];
        int dd[4] = {d4.x, d4.y, d4.z, d4.w};
        #pragma unroll
        for (int j = 0; j < 4; j++) {
            if (g_m1b[dd[j]]) {
                int e = t * 4 + j;
                int p = atomicAdd(&nloc1_sh, 1);
                if (p < E1CAP) e1loc[p] = e;
                else           g_e1[atomicAdd(&g_cnt[1], 1)] = e;   // spill (≈never)
                insert_s0(esrc[e]);
            }
        }
    }
    gsync();
    int nloc1 = min(nloc1_sh, E1CAP);

    // ---------- phase 3: scan0 over block slice -> local E0 list, then MLP -> h0 ----------
    {
        if (tid == 0) nloc0_sh = 0;
        __syncthreads();
        for (int t = sl_beg + tid; t < sl_end; t += TPB) {
            int4 d4 = ((const int4*)edst)[t];
            int dd[4] = {d4.x, d4.y, d4.z, d4.w};
            #pragma unroll
            for (int j = 0; j < 4; j++) {
                if (g_m0b[dd[j]]) e0loc[atomicAdd(&nloc0_sh, 1)] = t * 4 + j;
            }
        }
        __syncthreads();
        int nloc0 = nloc0_sh;   // capacity E0CAP == slice size, cannot overflow
        int slot = tid >> 5;            // 8 edge slots x 32 threads
        int c4   = (tid & 31) * 4;      // 128 cols / 4
        for (int base = 0; base < nloc0; base += 8) {
            int ne = min(8, nloc0 - base);
            if (tid < ne) {
                int e = e0loc[base + tid];
                int s = esrc[e];
                ss8[tid] = s; ds8[tid] = edst[e]; sea8[tid] = eattr[e];
                sent8[tid] = (int)x[s * 36 + 35];
            }
            __syncthreads();
            for (int idx = tid; idx < 8 * 52; idx += TPB) {
                int sl = idx / 52, j = idx % 52;
                float v = 0.f;
                if (sl < ne) {
                    if (j < 35)      v = x[ss8[sl] * 36 + j];
                    else if (j < 51) v = emb[sent8[sl] * 16 + (j - 35)];
                    else             v = sea8[sl];
                }
                sint[sl][j] = v;
            }
            __syncthreads();
            float4 acc = *(const float4*)&b1[c4];
            #pragma unroll 4
            for (int j = 0; j < 52; j++) {
                float4 w = *(const float4*)&w1[j * 128 + c4];
                float h = sint[slot][j];
                acc.x += h * w.x; acc.y += h * w.y; acc.z += h * w.z; acc.w += h * w.w;
            }
            acc.x = fmaxf(acc.x, 0.f); acc.y = fmaxf(acc.y, 0.f);
            acc.z = fmaxf(acc.z, 0.f); acc.w = fmaxf(acc.w, 0.f);
            *(float4*)&szt[slot][c4] = acc;
            __syncthreads();
            float4 a2 = *(const float4*)&bh[c4];
            #pragma unroll 16
            for (int j = 0; j < 128; j++) {
                float4 w = *(const float4*)&wh[j * 128 + c4];
                float h = szt[slot][j];
                a2.x += h * w.x; a2.y += h * w.y; a2.z += h * w.z; a2.w += h * w.w;
            }
            if (slot < ne) {
                float* hp = &g_h0[ds8[slot] * 128 + c4];
                atomicAdd(hp + 0, fmaxf(a2.x, 0.f));
                atomicAdd(hp + 1, fmaxf(a2.y, 0.f));
                atomicAdd(hp + 2, fmaxf(a2.z, 0.f));
                atomicAdd(hp + 3, fmaxf(a2.w, 0.f));
            }
            __syncthreads();
        }
    }
    gsync();

    // ---------- phase 4: kv1 over S0 (0-215) || q1 over S1 (216-255) || t1 (256-295) --------
    {
        int cntS0 = *(volatile int*)&g_cnt[3];
        int cntS1 = *(volatile int*)&g_cnt[4];
        if (bid < 216) {
            int slot = tid >> 7;            // 2 nodes/pass
            int m    = (tid >> 6) & 1;      // 0=k, 1=v
            int c4   = (tid & 63) * 4;
            const float* W  = m ? v1w : k1w;
            const float* Bb = m ? v1b : k1b;
            for (int base = bid * 2; base < cntS0; base += 216 * 2) {
                if (tid < 2) nsA[tid] = g_s0[min(base + tid, cntS0 - 1)];
                __syncthreads();
                for (int idx = tid; idx < 256; idx += TPB)
                    hrowA[idx >> 7][idx & 127] = g_h0[nsA[idx >> 7] * 128 + (idx & 127)];
                __syncthreads();
                float4 acc = *(const float4*)&Bb[c4];
                #pragma unroll 16
                for (int j = 0; j < 128; j++) {
                    float4 w = *(const float4*)&W[j * 256 + c4];
                    float h = hrowA[slot][j];
                    acc.x += h * w.x; acc.y += h * w.y; acc.z += h * w.z; acc.w += h * w.w;
                }
                if (base + slot < cntS0)
                    *(float4*)((m ? g_v : g_k) + nsA[slot] * 256 + c4) = acc;
                __syncthreads();
            }
        } else {
            bool is_t = bid >= 256;
            int bq = bid - (is_t ? 256 : 216);   // 0..39 each
            int slot = tid >> 6;                 // 4 nodes/pass
            int c4 = (tid & 63) * 4;
            const float* W  = is_t ? s1w : q1w;
            const float* Bb = is_t ? s1b : q1b;
            for (int base = bq * 4; base < cntS1; base += 40 * 4) {
                if (tid < 4) nsB[tid] = g_s1[min(base + tid, cntS1 - 1)];
                __syncthreads();
                for (int idx = tid; idx < 512; idx += TPB)
                    hq1[idx >> 7][idx & 127] = g_h0[nsB[idx >> 7] * 128 + (idx & 127)];
                __syncthreads();
                float4 acc = *(const float4*)&Bb[c4];
                #pragma unroll 16
                for (int j = 0; j < 128; j++) {
                    float4 w = *(const float4*)&W[j * 256 + c4];
                    float h = hq1[slot][j];
                    acc.x += h * w.x; acc.y += h * w.y; acc.z += h * w.z; acc.w += h * w.w;
                }
                if (base + slot < cntS1) {
                    if (is_t) *(float4*)&g_t1[(base + slot) * 256 + c4] = acc;
                    else      *(float4*)&g_q[nsB[slot] * 256 + c4] = acc;
                }
                __syncthreads();
            }
        }
    }
    gsync();

    // ---------- phase 5: local alpha+amax || spill alpha (tiny) ----------
    {
        for (int p = wid; p < nloc1 * 4; p += 8) {
            int k = p >> 2, h = p & 3;
            int e = e1loc[k];
            int s = esrc[e], d = edst[e];
            float ea = eattr[e];
            float d0 = 0.f;
            #pragma unroll
            for (int c0 = 0; c0 < 2; c0++) {
                int c = lane + c0 * 32;
                d0 += g_q[d * 256 + h * 64 + c] * (g_k[s * 256 + h * 64 + c] + ea * e1w[h * 64 + c]);
            }
            #pragma unroll
            for (int o = 16; o; o >>= 1) d0 += __shfl_xor_sync(0xffffffffu, d0, o);
            if (lane == 0) {
                float a = d0 * 0.125f;
                al1[k * 4 + h] = a;
                atomicMaxF(&g_amax[d * 4 + h], a);
            }
        }
        int nsp = *(volatile int*)&g_cnt[1];
        for (int t = gt; t < nsp * 4; t += NT) {
            int i = t >> 2, h = t & 3;
            int e = g_e1[i];
            int s = esrc[e], d = edst[e];
            float ea = eattr[e];
            const float4* qp = (const float4*)(g_q + d * 256 + h * 64);
            const float4* kp = (const float4*)(g_k + s * 256 + h * 64);
            const float4* ep = (const float4*)(e1w + h * 64);
            float dot = 0.f;
            #pragma unroll
            for (int c = 0; c < 16; c++) {
                float4 q = qp[c], k = kp[c], w = ep[c];
                dot += q.x * (k.x + ea * w.x) + q.y * (k.y + ea * w.y)
                     + q.z * (k.z + ea * w.z) + q.w * (k.w + ea * w.w);
            }
            float a = dot * 0.125f;
            g_alpha[t] = a;
            atomicMaxF(&g_amax[d * 4 + h], a);
        }
    }
    gsync();

    // ---------- phase 6: exp + sum + unnormalized message -> g_h1 (local + spill) ----------
    {
        int h = tid >> 6;
        for (int i = 0; i < nloc1; i++) {
            int e = e1loc[i];
            int s = esrc[e], d = edst[e];
            float ea = eattr[e];
            float ex = expf(al1[i * 4 + h] - g_amax[d * 4 + h]);
            if ((tid & 63) == 0) atomicAdd(&g_asum[d * 4 + h], ex);
            atomicAdd(&g_h1[d * 256 + tid], (g_v[s * 256 + tid] + ea * e1w[tid]) * ex);
        }
        int nsp = *(volatile int*)&g_cnt[1];
        for (int i = bid; i < nsp; i += GRID) {
            int e = g_e1[i];
            int s = esrc[e], d = edst[e];
            float ea = eattr[e];
            float ex = expf(g_alpha[i * 4 + h] - g_amax[d * 4 + h]);
            if ((tid & 63) == 0) atomicAdd(&g_asum[d * 4 + h], ex);
            atomicAdd(&g_h1[d * 256 + tid], (g_v[s * 256 + tid] + ea * e1w[tid]) * ex);
        }
    }
    gsync();

    // ---------- phase 7: kv2 over S1 (blocks 0-199) || q2 seeds (200-201)
    //                      || t2 seeds (202-203) || shadow counters (204) ----------
    {
        int cntS1 = *(volatile int*)&g_cnt[4];
        if (bid < 200) {
            int slot = tid >> 7;
            int m    = (tid >> 6) & 1;
            int c4   = (tid & 63) * 4;
            const float* W  = m ? v2w : k2w;
            const float* Bb = m ? v2b : k2b;
            for (int base = bid * 2; base < cntS1; base += 200 * 2) {
                if (tid < 2) {
                    int ii = min(base + tid, cntS1 - 1);
                    niA[tid] = ii; nsA[tid] = g_s1[ii];
                }
                __syncthreads();
                for (int idx = tid; idx < 512; idx += TPB) {
                    int sl = idx >> 8, j = idx & 255;
                    hrowB[sl][j] = h1val(nsA[sl], niA[sl], j);
                }
                __syncthreads();
                float4 acc = *(const float4*)&Bb[c4];
                #pragma unroll 16
                for (int j = 0; j < 256; j++) {
                    float4 w = *(const float4*)&W[j * 256 + c4];
                    float h = hrowB[slot][j];
                    acc.x += h * w.x; acc.y += h * w.y; acc.z += h * w.z; acc.w += h * w.w;
                }
                if (base + slot < cntS1)
                    *(float4*)((m ? g_v : g_k) + nsA[slot] * 256 + c4) = acc;
                __syncthreads();
            }
        } else if (bid < 204) {
            bool is_t = bid >= 202;
            int bq = (bid - (is_t ? 202 : 200));   // 0..1 -> seeds 0-3 / 4-7
            int slot = tid >> 6;
            int c4 = (tid & 63) * 4;
            int seed = bq * 4 + slot;
            if (tid < 4) {
                int sd = bq * 4 + tid;
                spB[tid] = g_spos1[sd];
                nsB[tid] = sd * NPGS + sa[sd];
            }
            __syncthreads();
            for (int idx = tid; idx < 1024; idx += TPB) {
                int sl = idx >> 8, j = idx & 255;
                hq2[sl][j] = h1val(nsB[sl], spB[sl], j);
            }
            __syncthreads();
            const float* W  = is_t ? s2w : q2w;
            const float* Bb = is_t ? s2b : q2b;
            float4 acc = *(const float4*)&Bb[c4];
            #pragma unroll 16
            for (int j = 0; j < 256; j++) {
                float4 w = *(const float4*)&W[j * 256 + c4];
                float h = hq2[slot][j];
                acc.x += h * w.x; acc.y += h * w.y; acc.z += h * w.z; acc.w += h * w.w;
            }
            if (is_t) *(float4*)&g_t2[seed * 256 + c4] = acc;
            else      *(float4*)&g_q[nsB[slot] * 256 + c4] = acc;
        } else if (bid == 204 && tid < 8) {
            g_cntS[tid] = g_cnt[tid];     // shadow for final phase
        }
    }
    gsync();

    // ---------- phase 8: attention+output (blocks 0-7) || cleanup (blocks 8+) ----------
    if (bid < 8) {
        int b = bid;
        int n = b * NPGS + sa[b];
        int cnt = g_cntS[0]; if (cnt > 256) cnt = 256;
        if (tid < cnt) {
            int e = g_e2[tid];
            sd_all[tid] = edst[e]; ss_all[tid] = esrc[e]; sea_all[tid] = eattr[e];
        }
        __syncthreads();
        if (tid == 0) {
            int p = 0;
            for (int i = 0; i < cnt; i++)
                if ((sd_all[i] >> 13) == b && p < 64) { ssrc_s[p] = ss_all[i]; seaa[p] = sea_all[i]; p++; }
            ne_sh = p;
        }
        __syncthreads();
        int ne = ne_sh;
        for (int p = wid; p < ne * 4; p += 8) {
            int k = p >> 2, h = p & 3;
            int s = ssrc_s[k]; float ea = seaa[k];
            float d0 = 0.f;
            #pragma unroll
            for (int c0 = 0; c0 < 2; c0++) {
                int c = lane + c0 * 32;
                d0 += g_q[n * 256 + h * 64 + c] * (g_k[s * 256 + h * 64 + c] + ea * e2w[h * 64 + c]);
            }
            #pragma unroll
            for (int o = 16; o; o >>= 1) d0 += __shfl_xor_sync(0xffffffffu, d0, o);
            if (lane == 0) sal[h][k] = d0 * 0.125f;
        }
        __syncthreads();
        if (tid < 4) {
            float m = NEG_INF;
            for (int k = 0; k < ne; k++) m = fmaxf(m, sal[tid][k]);
            float s = 0.f;
            for (int k = 0; k < ne; k++) { float ex = expf(sal[tid][k] - m); sal[tid][k] = ex; s += ex; }
            float inv = 1.f / (s + 1e-16f);
            for (int k = 0; k < ne; k++) sal[tid][k] *= inv;
        }
        __syncthreads();
        int h = tid >> 6;
        float acc = 0.f;
        for (int k = 0; k < ne; k++)
            acc += (g_v[ssrc_s[k] * 256 + tid] + seaa[k] * e2w[tid]) * sal[h][k];
        out[b * 256 + tid] = fmaxf(acc + g_t2[b * 256 + tid], 0.f);
    } else {
        // cleanup: restore canonical all-zero flag/counter state for the next replay
        int c0 = g_cntS[3], c1 = g_cntS[4];
        for (int i = (bid - 8) * TPB + tid; i < c0; i += (GRID - 8) * TPB) {
            int nn2 = g_s0[i];
            g_m0[nn2] = 0; g_m0b[nn2] = 0;
        }
        for (int i = (bid - 8) * TPB + tid; i < c1; i += (GRID - 8) * TPB) {
            int nn2 = g_s1[i];
            g_m1[nn2] = 0; g_m1b[nn2] = 0;
        }
        if (bid == 8 && tid < 8) g_cnt[tid] = 0;
    }
}

// ---------------- launch ----------------
extern "C" void kernel_launch(void* const* d_in, const int* in_sizes, int n_in,
                              void* d_out, int out_size) {
    const float* x     = (const float*)d_in[0];
    const int*   esrc  = (const int*)d_in[1];
    const int*   edst  = (const int*)d_in[2];
    const float* eattr = (const float*)d_in[3];
    const int*   aid   = (const int*)d_in[4];
    const float* emb   = (const float*)d_in[5];
    const float* w1    = (const float*)d_in[6];
    const float* b1    = (const float*)d_in[7];
    const float* wh    = (const float*)d_in[8];
    const float* bh    = (const float*)d_in[9];
    const float* q1w = (const float*)d_in[10], *q1b = (const float*)d_in[11];
    const float* k1w = (const float*)d_in[12], *k1b = (const float*)d_in[13];
    const float* v1w = (const float*)d_in[14], *v1b = (const float*)d_in[15];
    const float* e1w = (const float*)d_in[16];
    const float* s1w = (const float*)d_in[17], *s1b = (const float*)d_in[18];
    const float* q2w = (const float*)d_in[19], *q2b = (const float*)d_in[20];
    const float* k2w = (const float*)d_in[21], *k2b = (const float*)d_in[22];
    const float* v2w = (const float*)d_in[23], *v2b = (const float*)d_in[24];
    const float* e2w = (const float*)d_in[25];
    const float* s2w = (const float*)d_in[26], *s2b = (const float*)d_in[27];
    float* out = (float*)d_out;

    k_mega<<<GRID, TPB>>>(x, esrc, edst, eattr, aid, emb, w1, b1, wh, bh,
                          q1w, q1b, k1w, k1b, v1w, v1b, e1w, s1w, s1b,
                          q2w, q2b, k2w, k2b, v2w, v2b, e2w, s2w, s2b, out);
}

// round 16
// speedup vs baseline: 1.1450x; 1.0787x over previous
#include <cuda_runtime.h>
#include <math.h>

#define NN 65536
#define EE 262144
#define NPGS 8192
#define GRID 296
#define TPB 256
#define NT (GRID * TPB)
#define SLICE4 222            // int4 loads per block slice (222*4 = 888 edges)
#define E0CAP 888
#define E1CAP 384
#define NEG_INF __int_as_float(0xff800000)

// ---------------- scratch (device globals; canonical state between replays = all zeros) ----
__device__ __align__(16) int            g_m1[NN], g_m0[NN];
__device__ __align__(16) unsigned char  g_m1b[NN], g_m0b[NN];
__device__ __align__(16) int   g_e1[EE], g_e2[EE];    // g_e1 = SPILL-only
__device__ __align__(16) int   g_s0[NN], g_s1[NN];
__device__ __align__(16) int   g_cnt[8];    // 0:nE2 1:nE1spill 3:nS0 4:nS1 (zeroed by cleanup)
__device__ __align__(16) int   g_cntS[8];   // shadow for final phase
__device__ int   g_spos1[8];                 // S1 list position of each seed
__device__ __align__(16) float g_h0[NN * 128];
__device__ __align__(16) float g_h1[NN * 256];   // layer-1 message numerator (raw-exp weighted)
__device__ __align__(16) float g_q[NN * 256];
__device__ __align__(16) float g_k[NN * 256];
__device__ __align__(16) float g_v[NN * 256];
__device__ __align__(16) float g_t1[NN * 256];   // skip GEMV, indexed by S1 list position
__device__ __align__(16) float g_t2[8 * 256];
__device__ __align__(16) float g_asum[NN * 4];   // sum of raw exps per (dst, head)

// software grid barrier (generation-based; generation persists across replays)
__device__ unsigned          g_bar_cnt;
__device__ volatile unsigned g_bar_gen;

__device__ __forceinline__ void gsync() {
    __syncthreads();
    if (threadIdx.x == 0) {
        __threadfence();
        unsigned gen = g_bar_gen;
        if (atomicAdd(&g_bar_cnt, 1u) == GRID - 1) {
            g_bar_cnt = 0;
            __threadfence();
            g_bar_gen = gen + 1;
        } else {
            int spins = 0;
            while (g_bar_gen == gen) {
                if (++spins > 64) { __nanosleep(16); spins = 0; }
            }
            __threadfence();
        }
    }
    __syncthreads();
}

__device__ __forceinline__ void zero_row_h1(int n) {
    float4 z = make_float4(0.f, 0.f, 0.f, 0.f);
    float4* p = (float4*)&g_h1[n * 256];
    #pragma unroll 8
    for (int q = 0; q < 64; q++) p[q] = z;
    ((float4*)&g_asum[n * 4])[0] = z;
}
__device__ __forceinline__ void zero_row_h0(int n) {
    float4 z = make_float4(0.f, 0.f, 0.f, 0.f);
    float4* p = (float4*)&g_h0[n * 128];
    #pragma unroll 8
    for (int q = 0; q < 32; q++) p[q] = z;
}

__device__ __forceinline__ void insert_s1(int s, const int* sa) {
    if (atomicExch(&g_m1[s], 1) == 0) {
        g_m1b[s] = 1;
        int p = atomicAdd(&g_cnt[4], 1);
        g_s1[p] = s;
        if ((s & 8191) == sa[s >> 13]) g_spos1[s >> 13] = p;
        zero_row_h1(s);
    }
}
__device__ __forceinline__ void insert_s0(int s) {
    if (atomicExch(&g_m0[s], 1) == 0) {
        g_m0b[s] = 1;
        g_s0[atomicAdd(&g_cnt[3], 1)] = s;
        zero_row_h0(s);
    }
}

// h1 final value on the fly: relu(num/asum + t1[list_pos])
__device__ __forceinline__ float h1val(int n, int i, int j) {
    return fmaxf(g_h1[n * 256 + j] / (g_asum[n * 4 + (j >> 6)] + 1e-16f)
                 + g_t1[i * 256 + j], 0.f);
}

// ==================== single persistent megakernel ====================
__global__ void __launch_bounds__(TPB, 2)
k_mega(const float* __restrict__ x, const int* __restrict__ esrc,
       const int* __restrict__ edst, const float* __restrict__ eattr,
       const int* __restrict__ aid, const float* __restrict__ emb,
       const float* __restrict__ w1, const float* __restrict__ b1,
       const float* __restrict__ wh, const float* __restrict__ bh,
       const float* __restrict__ q1w, const float* __restrict__ q1b,
       const float* __restrict__ k1w, const float* __restrict__ k1b,
       const float* __restrict__ v1w, const float* __restrict__ v1b,
       const float* __restrict__ e1w,
       const float* __restrict__ s1w, const float* __restrict__ s1b,
       const float* __restrict__ q2w, const float* __restrict__ q2b,
       const float* __restrict__ k2w, const float* __restrict__ k2b,
       const float* __restrict__ v2w, const float* __restrict__ v2b,
       const float* __restrict__ e2w,
       const float* __restrict__ s2w, const float* __restrict__ s2b,
       float* __restrict__ out) {
    __shared__ int   sa[8];
    __shared__ int   e0loc[E0CAP];                  // block-local E0 edge list
    __shared__ int   e1loc[E1CAP];                  // block-local E1 edge list
    __shared__ float al1[E1CAP * 4];                // local exp(alpha) per head
    __shared__ int   nloc0_sh, nloc1_sh;
    __shared__ __align__(16) float sint[8][52];
    __shared__ __align__(16) float szt[8][128];
    __shared__ int   ss8[8], ds8[8], sent8[8];
    __shared__ float sea8[8];
    __shared__ __align__(16) float hrowA[2][128];
    __shared__ __align__(16) float hq1[4][128];
    __shared__ __align__(16) float hrowB[2][256];
    __shared__ __align__(16) float hq2[4][256];
    __shared__ int   nsA[2], niA[2], nsB[4], spB[4];
    __shared__ int   sd_all[256], ss_all[256];
    __shared__ float sea_all[256];
    __shared__ int   ssrc_s[64];
    __shared__ float seaa[64];
    __shared__ float sal[4][64];
    __shared__ int   ne_sh;

    int tid = threadIdx.x, bid = blockIdx.x;
    int gt  = bid * TPB + tid;
    int wid = tid >> 5, lane = tid & 31;

    if (tid < 8) sa[tid] = aid[tid];
    __syncthreads();

    // slice bounds (int4 units) for block-local scans
    int sl_beg = bid * SLICE4;
    int sl_end = min(EE / 4, sl_beg + SLICE4);

    // ---------- phase 1: seeds + scan2 (dst in S2 arithmetically; grow S1, S0) ----------
    if (bid == 0 && tid < 8) {
        int n = tid * NPGS + sa[tid];
        insert_s1(n, sa);
        insert_s0(n);
    }
    for (int t = gt; t < EE / 4; t += NT) {
        int4 d4 = ((const int4*)edst)[t];
        int dd[4] = {d4.x, d4.y, d4.z, d4.w};
        #pragma unroll
        for (int j = 0; j < 4; j++) {
            int d = dd[j];
            if ((d & 8191) == sa[d >> 13]) {
                int e = t * 4 + j;
                g_e2[atomicAdd(&g_cnt[0], 1)] = e;
                int s = esrc[e];
                insert_s1(s, sa);
                insert_s0(s);
            }
        }
    }
    gsync();

    // ---------- phase 2: scan1 over block slice -> local E1 list; grow S0 ----------
    if (tid == 0) nloc1_sh = 0;
    __syncthreads();
    for (int t = sl_beg + tid; t < sl_end; t += TPB) {
        int4 d4 = ((const int4*)edst)[t];
        int dd[4] = {d4.x, d4.y, d4.z, d4.w};
        #pragma unroll
        for (int j = 0; j < 4; j++) {
            if (g_m1b[dd[j]]) {
                int e = t * 4 + j;
                int p = atomicAdd(&nloc1_sh, 1);
                if (p < E1CAP) e1loc[p] = e;
                else           g_e1[atomicAdd(&g_cnt[1], 1)] = e;   // spill (≈never)
                insert_s0(esrc[e]);
            }
        }
    }
    gsync();
    int nloc1 = min(nloc1_sh, E1CAP);

    // ---------- phase 3: scan0 over block slice -> local E0 list, then MLP -> h0 ----------
    {
        if (tid == 0) nloc0_sh = 0;
        __syncthreads();
        for (int t = sl_beg + tid; t < sl_end; t += TPB) {
            int4 d4 = ((const int4*)edst)[t];
            int dd[4] = {d4.x, d4.y, d4.z, d4.w};
            #pragma unroll
            for (int j = 0; j < 4; j++) {
                if (g_m0b[dd[j]]) e0loc[atomicAdd(&nloc0_sh, 1)] = t * 4 + j;
            }
        }
        __syncthreads();
        int nloc0 = nloc0_sh;   // capacity E0CAP == slice size, cannot overflow
        int slot = tid >> 5;            // 8 edge slots x 32 threads
        int c4   = (tid & 31) * 4;      // 128 cols / 4
        for (int base = 0; base < nloc0; base += 8) {
            int ne = min(8, nloc0 - base);
            if (tid < ne) {
                int e = e0loc[base + tid];
                int s = esrc[e];
                ss8[tid] = s; ds8[tid] = edst[e]; sea8[tid] = eattr[e];
                sent8[tid] = (int)x[s * 36 + 35];
            }
            __syncthreads();
            for (int idx = tid; idx < 8 * 52; idx += TPB) {
                int sl = idx / 52, j = idx % 52;
                float v = 0.f;
                if (sl < ne) {
                    if (j < 35)      v = x[ss8[sl] * 36 + j];
                    else if (j < 51) v = emb[sent8[sl] * 16 + (j - 35)];
                    else             v = sea8[sl];
                }
                sint[sl][j] = v;
            }
            __syncthreads();
            float4 acc = *(const float4*)&b1[c4];
            #pragma unroll 4
            for (int j = 0; j < 52; j++) {
                float4 w = *(const float4*)&w1[j * 128 + c4];
                float h = sint[slot][j];
                acc.x += h * w.x; acc.y += h * w.y; acc.z += h * w.z; acc.w += h * w.w;
            }
            acc.x = fmaxf(acc.x, 0.f); acc.y = fmaxf(acc.y, 0.f);
            acc.z = fmaxf(acc.z, 0.f); acc.w = fmaxf(acc.w, 0.f);
            *(float4*)&szt[slot][c4] = acc;
            __syncthreads();
            float4 a2 = *(const float4*)&bh[c4];
            #pragma unroll 16
            for (int j = 0; j < 128; j++) {
                float4 w = *(const float4*)&wh[j * 128 + c4];
                float h = szt[slot][j];
                a2.x += h * w.x; a2.y += h * w.y; a2.z += h * w.z; a2.w += h * w.w;
            }
            if (slot < ne) {
                float* hp = &g_h0[ds8[slot] * 128 + c4];
                atomicAdd(hp + 0, fmaxf(a2.x, 0.f));
                atomicAdd(hp + 1, fmaxf(a2.y, 0.f));
                atomicAdd(hp + 2, fmaxf(a2.z, 0.f));
                atomicAdd(hp + 3, fmaxf(a2.w, 0.f));
            }
            __syncthreads();
        }
    }
    gsync();

    // ---------- phase 4: kv1 over S0 (0-215) || q1 over S1 (216-255) || t1 (256-295) --------
    {
        int cntS0 = *(volatile int*)&g_cnt[3];
        int cntS1 = *(volatile int*)&g_cnt[4];
        if (bid < 216) {
            int slot = tid >> 7;            // 2 nodes/pass
            int m    = (tid >> 6) & 1;      // 0=k, 1=v
            int c4   = (tid & 63) * 4;
            const float* W  = m ? v1w : k1w;
            const float* Bb = m ? v1b : k1b;
            for (int base = bid * 2; base < cntS0; base += 216 * 2) {
                if (tid < 2) nsA[tid] = g_s0[min(base + tid, cntS0 - 1)];
                __syncthreads();
                for (int idx = tid; idx < 256; idx += TPB)
                    hrowA[idx >> 7][idx & 127] = g_h0[nsA[idx >> 7] * 128 + (idx & 127)];
                __syncthreads();
                float4 acc = *(const float4*)&Bb[c4];
                #pragma unroll 16
                for (int j = 0; j < 128; j++) {
                    float4 w = *(const float4*)&W[j * 256 + c4];
                    float h = hrowA[slot][j];
                    acc.x += h * w.x; acc.y += h * w.y; acc.z += h * w.z; acc.w += h * w.w;
                }
                if (base + slot < cntS0)
                    *(float4*)((m ? g_v : g_k) + nsA[slot] * 256 + c4) = acc;
                __syncthreads();
            }
        } else {
            bool is_t = bid >= 256;
            int bq = bid - (is_t ? 256 : 216);   // 0..39 each
            int slot = tid >> 6;                 // 4 nodes/pass
            int c4 = (tid & 63) * 4;
            const float* W  = is_t ? s1w : q1w;
            const float* Bb = is_t ? s1b : q1b;
            for (int base = bq * 4; base < cntS1; base += 40 * 4) {
                if (tid < 4) nsB[tid] = g_s1[min(base + tid, cntS1 - 1)];
                __syncthreads();
                for (int idx = tid; idx < 512; idx += TPB)
                    hq1[idx >> 7][idx & 127] = g_h0[nsB[idx >> 7] * 128 + (idx & 127)];
                __syncthreads();
                float4 acc = *(const float4*)&Bb[c4];
                #pragma unroll 16
                for (int j = 0; j < 128; j++) {
                    float4 w = *(const float4*)&W[j * 256 + c4];
                    float h = hq1[slot][j];
                    acc.x += h * w.x; acc.y += h * w.y; acc.z += h * w.z; acc.w += h * w.w;
                }
                if (base + slot < cntS1) {
                    if (is_t) *(float4*)&g_t1[(base + slot) * 256 + c4] = acc;
                    else      *(float4*)&g_q[nsB[slot] * 256 + c4] = acc;
                }
                __syncthreads();
            }
        }
    }
    gsync();

    // ---------- phase 5: raw-exp alpha (block-local) + message + asum; spill inline ----------
    {
        for (int p = wid; p < nloc1 * 4; p += 8) {
            int k = p >> 2, h = p & 3;
            int e = e1loc[k];
            int s = esrc[e], d = edst[e];
            float ea = eattr[e];
            float d0 = 0.f;
            #pragma unroll
            for (int c0 = 0; c0 < 2; c0++) {
                int c = lane + c0 * 32;
                d0 += g_q[d * 256 + h * 64 + c] * (g_k[s * 256 + h * 64 + c] + ea * e1w[h * 64 + c]);
            }
            #pragma unroll
            for (int o = 16; o; o >>= 1) d0 += __shfl_xor_sync(0xffffffffu, d0, o);
            if (lane == 0) al1[k * 4 + h] = expf(d0 * 0.125f);
        }
        __syncthreads();
        int h = tid >> 6;
        for (int i = 0; i < nloc1; i++) {
            int e = e1loc[i];
            int s = esrc[e], d = edst[e];
            float ea = eattr[e];
            float ex = al1[i * 4 + h];
            if ((tid & 63) == 0) atomicAdd(&g_asum[d * 4 + h], ex);
            atomicAdd(&g_h1[d * 256 + tid], (g_v[s * 256 + tid] + ea * e1w[tid]) * ex);
        }
        // spill path (≈ always empty): per-thread redundant dot, no block sync needed
        int nsp = *(volatile int*)&g_cnt[1];
        for (int i = bid; i < nsp; i += GRID) {
            int e = g_e1[i];
            int s = esrc[e], d = edst[e];
            float ea = eattr[e];
            float dot = 0.f;
            for (int c = 0; c < 64; c++)
                dot += g_q[d * 256 + h * 64 + c] * (g_k[s * 256 + h * 64 + c] + ea * e1w[h * 64 + c]);
            float ex = expf(dot * 0.125f);
            if ((tid & 63) == 0) atomicAdd(&g_asum[d * 4 + h], ex);
            atomicAdd(&g_h1[d * 256 + tid], (g_v[s * 256 + tid] + ea * e1w[tid]) * ex);
        }
    }
    gsync();

    // ---------- phase 6: kv2 over S1 (blocks 0-199) || q2 seeds (200-201)
    //                      || t2 seeds (202-203) || shadow counters (204) ----------
    {
        int cntS1 = *(volatile int*)&g_cnt[4];
        if (bid < 200) {
            int slot = tid >> 7;
            int m    = (tid >> 6) & 1;
            int c4   = (tid & 63) * 4;
            const float* W  = m ? v2w : k2w;
            const float* Bb = m ? v2b : k2b;
            for (int base = bid * 2; base < cntS1; base += 200 * 2) {
                if (tid < 2) {
                    int ii = min(base + tid, cntS1 - 1);
                    niA[tid] = ii; nsA[tid] = g_s1[ii];
                }
                __syncthreads();
                for (int idx = tid; idx < 512; idx += TPB) {
                    int sl = idx >> 8, j = idx & 255;
                    hrowB[sl][j] = h1val(nsA[sl], niA[sl], j);
                }
                __syncthreads();
                float4 acc = *(const float4*)&Bb[c4];
                #pragma unroll 16
                for (int j = 0; j < 256; j++) {
                    float4 w = *(const float4*)&W[j * 256 + c4];
                    float h = hrowB[slot][j];
                    acc.x += h * w.x; acc.y += h * w.y; acc.z += h * w.z; acc.w += h * w.w;
                }
                if (base + slot < cntS1)
                    *(float4*)((m ? g_v : g_k) + nsA[slot] * 256 + c4) = acc;
                __syncthreads();
            }
        } else if (bid < 204) {
            bool is_t = bid >= 202;
            int bq = (bid - (is_t ? 202 : 200));   // 0..1 -> seeds 0-3 / 4-7
            int slot = tid >> 6;
            int c4 = (tid & 63) * 4;
            int seed = bq * 4 + slot;
            if (tid < 4) {
                int sd = bq * 4 + tid;
                spB[tid] = g_spos1[sd];
                nsB[tid] = sd * NPGS + sa[sd];
            }
            __syncthreads();
            for (int idx = tid; idx < 1024; idx += TPB) {
                int sl = idx >> 8, j = idx & 255;
                hq2[sl][j] = h1val(nsB[sl], spB[sl], j);
            }
            __syncthreads();
            const float* W  = is_t ? s2w : q2w;
            const float* Bb = is_t ? s2b : q2b;
            float4 acc = *(const float4*)&Bb[c4];
            #pragma unroll 16
            for (int j = 0; j < 256; j++) {
                float4 w = *(const float4*)&W[j * 256 + c4];
                float h = hq2[slot][j];
                acc.x += h * w.x; acc.y += h * w.y; acc.z += h * w.z; acc.w += h * w.w;
            }
            if (is_t) *(float4*)&g_t2[seed * 256 + c4] = acc;
            else      *(float4*)&g_q[nsB[slot] * 256 + c4] = acc;
        } else if (bid == 204 && tid < 8) {
            g_cntS[tid] = g_cnt[tid];     // shadow for final phase
        }
    }
    gsync();

    // ---------- phase 7: attention+output (blocks 0-7) || cleanup (blocks 8+) ----------
    if (bid < 8) {
        int b = bid;
        int n = b * NPGS + sa[b];
        int cnt = g_cntS[0]; if (cnt > 256) cnt = 256;
        if (tid < cnt) {
            int e = g_e2[tid];
            sd_all[tid] = edst[e]; ss_all[tid] = esrc[e]; sea_all[tid] = eattr[e];
        }
        __syncthreads();
        if (tid == 0) {
            int p = 0;
            for (int i = 0; i < cnt; i++)
                if ((sd_all[i] >> 13) == b && p < 64) { ssrc_s[p] = ss_all[i]; seaa[p] = sea_all[i]; p++; }
            ne_sh = p;
        }
        __syncthreads();
        int ne = ne_sh;
        for (int p = wid; p < ne * 4; p += 8) {
            int k = p >> 2, h = p & 3;
            int s = ssrc_s[k]; float ea = seaa[k];
            float d0 = 0.f;
            #pragma unroll
            for (int c0 = 0; c0 < 2; c0++) {
                int c = lane + c0 * 32;
                d0 += g_q[n * 256 + h * 64 + c] * (g_k[s * 256 + h * 64 + c] + ea * e2w[h * 64 + c]);
            }
            #pragma unroll
            for (int o = 16; o; o >>= 1) d0 += __shfl_xor_sync(0xffffffffu, d0, o);
            if (lane == 0) sal[h][k] = d0 * 0.125f;
        }
        __syncthreads();
        if (tid < 4) {
            float m = NEG_INF;
            for (int k = 0; k < ne; k++) m = fmaxf(m, sal[tid][k]);
            float s = 0.f;
            for (int k = 0; k < ne; k++) { float ex = expf(sal[tid][k] - m); sal[tid][k] = ex; s += ex; }
            float inv = 1.f / (s + 1e-16f);
            for (int k = 0; k < ne; k++) sal[tid][k] *= inv;
        }
        __syncthreads();
        int h = tid >> 6;
        float acc = 0.f;
        for (int k = 0; k < ne; k++)
            acc += (g_v[ssrc_s[k] * 256 + tid] + seaa[k] * e2w[tid]) * sal[h][k];
        out[b * 256 + tid] = fmaxf(acc + g_t2[b * 256 + tid], 0.f);
    } else {
        // cleanup: restore canonical all-zero flag/counter state for the next replay
        int c0 = g_cntS[3], c1 = g_cntS[4];
        for (int i = (bid - 8) * TPB + tid; i < c0; i += (GRID - 8) * TPB) {
            int nn2 = g_s0[i];
            g_m0[nn2] = 0; g_m0b[nn2] = 0;
        }
        for (int i = (bid - 8) * TPB + tid; i < c1; i += (GRID - 8) * TPB) {
            int nn2 = g_s1[i];
            g_m1[nn2] = 0; g_m1b[nn2] = 0;
        }
        if (bid == 8 && tid < 8) g_cnt[tid] = 0;
    }
}

// ---------------- launch ----------------
extern "C" void kernel_launch(void* const* d_in, const int* in_sizes, int n_in,
                              void* d_out, int out_size) {
    const float* x     = (const float*)d_in[0];
    const int*   esrc  = (const int*)d_in[1];
    const int*   edst  = (const int*)d_in[2];
    const float* eattr = (const float*)d_in[3];
    const int*   aid   = (const int*)d_in[4];
    const float* emb   = (const float*)d_in[5];
    const float* w1    = (const float*)d_in[6];
    const float* b1    = (const float*)d_in[7];
    const float* wh    = (const float*)d_in[8];
    const float* bh    = (const float*)d_in[9];
    const float* q1w = (const float*)d_in[10], *q1b = (const float*)d_in[11];
    const float* k1w = (const float*)d_in[12], *k1b = (const float*)d_in[13];
    const float* v1w = (const float*)d_in[14], *v1b = (const float*)d_in[15];
    const float* e1w = (const float*)d_in[16];
    const float* s1w = (const float*)d_in[17], *s1b = (const float*)d_in[18];
    const float* q2w = (const float*)d_in[19], *q2b = (const float*)d_in[20];
    const float* k2w = (const float*)d_in[21], *k2b = (const float*)d_in[22];
    const float* v2w = (const float*)d_in[23], *v2b = (const float*)d_in[24];
    const float* e2w = (const float*)d_in[25];
    const float* s2w = (const float*)d_in[26], *s2b = (const float*)d_in[27];
    float* out = (float*)d_out;

    k_mega<<<GRID, TPB>>>(x, esrc, edst, eattr, aid, emb, w1, b1, wh, bh,
                          q1w, q1b, k1w, k1b, v1w, v1b, e1w, s1w, s1b,
                          q2w, q2b, k2w, k2b, v2w, v2b, e2w, s2w, s2b, out);
}